// round 1
// baseline (speedup 1.0000x reference)
#include <cuda_runtime.h>
#include <math.h>

// Problem constants
namespace {
constexpr int kB  = 32;
constexpr int kS  = 2048;
constexpr int kD  = 1024;
constexpr int kBN = 64;
constexpr int kE  = 8;

// Main-kernel tiling
constexpr int TS = 64;               // S-rows per block
constexpr int KC = 32;               // k-chunk (phase A over D, phase B over 128)
constexpr int XS_STRIDE = TS + 4;    // 68 (16B-aligned rows, 4-way store conflicts only)
constexpr int WS_STRIDE = 128 + 4;   // 132
constexpr int HS_STRIDE = TS;        // 64

constexpr int SMEM_FLOATS = KC * WS_STRIDE + KC * XS_STRIDE + 128 * HS_STRIDE;
constexpr int SMEM_BYTES  = SMEM_FLOATS * 4;   // 58368 B -> dynamic smem
}

// Scratch (no allocation allowed -> device globals)
__device__ float g_pooled[kB * kD];
__device__ int   g_top_i[kB * 2];
__device__ float g_top_w[kB * 2];

// ---------------------------------------------------------------------------
// Kernel 1: pooled = mean over S.  grid = (D/256, B), 256 threads.
// ---------------------------------------------------------------------------
__global__ void pool_kernel(const float* __restrict__ x) {
    int d = blockIdx.x * blockDim.x + threadIdx.x;
    int b = blockIdx.y;
    const float* xp = x + (size_t)b * kS * kD + d;
    float acc[8] = {0.f, 0.f, 0.f, 0.f, 0.f, 0.f, 0.f, 0.f};
#pragma unroll 1
    for (int s = 0; s < kS; s += 8) {
#pragma unroll
        for (int u = 0; u < 8; u++)
            acc[u] += xp[(size_t)(s + u) * kD];
    }
    float t = 0.f;
#pragma unroll
    for (int u = 0; u < 8; u++) t += acc[u];
    g_pooled[b * kD + d] = t * (1.0f / kS);
}

// ---------------------------------------------------------------------------
// Kernel 2: routing. 1 block, 32 warps; warp w handles batch b = w.
// ---------------------------------------------------------------------------
__global__ void route_kernel(const float* __restrict__ gate_w) {
    int b    = threadIdx.x >> 5;
    int lane = threadIdx.x & 31;

    float logits[kE];
#pragma unroll
    for (int e = 0; e < kE; e++) {
        float acc = 0.f;
        for (int d = lane; d < kD; d += 32)
            acc += g_pooled[b * kD + d] * gate_w[e * kD + d];
#pragma unroll
        for (int off = 16; off; off >>= 1)
            acc += __shfl_xor_sync(0xFFFFFFFFu, acc, off);
        logits[e] = acc;
    }

    if (lane == 0) {
        float mx = logits[0];
#pragma unroll
        for (int e = 1; e < kE; e++) mx = fmaxf(mx, logits[e]);
        float p[kE], sum = 0.f;
#pragma unroll
        for (int e = 0; e < kE; e++) { p[e] = expf(logits[e] - mx); sum += p[e]; }
        float inv_sum = 1.f / sum;
#pragma unroll
        for (int e = 0; e < kE; e++) p[e] *= inv_sum;

        int i0 = 0;
#pragma unroll
        for (int e = 1; e < kE; e++) if (p[e] > p[i0]) i0 = e;
        int i1 = (i0 == 0) ? 1 : 0;
#pragma unroll
        for (int e = 0; e < kE; e++) if (e != i0 && p[e] > p[i1]) i1 = e;

        float w0 = p[i0], w1 = p[i1];
        float inv = 1.f / (w0 + w1 + 1e-8f);
        g_top_i[b * 2 + 0] = i0;
        g_top_i[b * 2 + 1] = i1;
        g_top_w[b * 2 + 0] = w0 * inv;
        g_top_w[b * 2 + 1] = w1 * inv;
    }
}

// ---------------------------------------------------------------------------
// Kernel 3: fused per-tile expert MLP.
// grid = (S/TS, B), 256 threads (16x16 -> 4x8 register micro-tile).
// Phase A: h[c'][s] = gelu(x @ Wd^T + bd) * w_k for both experts (c' in 0..127)
// Phase B: out[s][d] = sum_c' h[c'][s] * Wu_cat[d][c'] + combined up-bias
// ---------------------------------------------------------------------------
__global__ __launch_bounds__(256, 3)
void moe_main(const float* __restrict__ x,
              const float* __restrict__ down_w,
              const float* __restrict__ down_b,
              const float* __restrict__ up_w,
              const float* __restrict__ up_b,
              float* __restrict__ out)
{
    extern __shared__ float smem[];
    float* ws = smem;                              // [KC][WS_STRIDE]  (reused in B)
    float* xs = smem + KC * WS_STRIDE;             // [KC][XS_STRIDE]  (phase A only)
    float* hs = smem + KC * WS_STRIDE + KC * XS_STRIDE;  // [128][HS_STRIDE]

    const int b  = blockIdx.y;
    const int s0 = blockIdx.x * TS;
    const int tid = threadIdx.x;
    const int tr  = tid >> 4;   // 0..15: owns rows tr*4 .. tr*4+3
    const int tc  = tid & 15;   // 0..15: owns cols tc*8 .. tc*8+7
    const int lk   = tid & 31;  // load lane: k-index
    const int lrow = tid >> 5;  // load row group: 0..7

    const int   e0 = g_top_i[b * 2 + 0];
    const int   e1 = g_top_i[b * 2 + 1];
    const float w0 = g_top_w[b * 2 + 0];
    const float w1 = g_top_w[b * 2 + 1];

    const float* xb = x + ((size_t)b * kS + s0) * kD;

    float acc[4][8];
#pragma unroll
    for (int i = 0; i < 4; i++)
#pragma unroll
        for (int j = 0; j < 8; j++) acc[i][j] = 0.f;

    // ---------------- Phase A: h accumulation (M=64, N=128, K=1024) ----------
    const float* wd0 = down_w + (size_t)e0 * kBN * kD + lk;
    const float* wd1 = down_w + (size_t)e1 * kBN * kD + lk;

    for (int kc = 0; kc < kD; kc += KC) {
        // stage x tile (k-major): xs[kk][s]
#pragma unroll
        for (int r = 0; r < 8; r++) {
            int s = lrow + r * 8;
            xs[lk * XS_STRIDE + s] = xb[(size_t)s * kD + kc + lk];
        }
        // stage Wd tile (k-major): ws[kk][c'] for both experts
#pragma unroll
        for (int r = 0; r < 8; r++) {
            int c = lrow + r * 8;                 // 0..63
            ws[lk * WS_STRIDE + c]      = wd0[(size_t)c * kD + kc];
            ws[lk * WS_STRIDE + 64 + c] = wd1[(size_t)c * kD + kc];
        }
        __syncthreads();

#pragma unroll 8
        for (int kk = 0; kk < KC; kk++) {
            float4 a4 = *(const float4*)(xs + kk * XS_STRIDE + (tr << 2));
            float4 bL = *(const float4*)(ws + kk * WS_STRIDE + (tc << 3));
            float4 bR = *(const float4*)(ws + kk * WS_STRIDE + (tc << 3) + 4);
            float a[4] = {a4.x, a4.y, a4.z, a4.w};
            float bb[8] = {bL.x, bL.y, bL.z, bL.w, bR.x, bR.y, bR.z, bR.w};
#pragma unroll
            for (int i = 0; i < 4; i++)
#pragma unroll
                for (int j = 0; j < 8; j++)
                    acc[i][j] = fmaf(a[i], bb[j], acc[i][j]);
        }
        __syncthreads();
    }

    // Epilogue A: bias + exact GELU + routing weight -> hs[c'][s]
#pragma unroll
    for (int j = 0; j < 8; j++) {
        int c = (tc << 3) + j;                    // 0..127
        int e  = (c < 64) ? e0 : e1;
        float wk = (c < 64) ? w0 : w1;
        float bd = down_b[e * kBN + (c & 63)];
        float4 hv;
        float v0 = acc[0][j] + bd;
        float v1 = acc[1][j] + bd;
        float v2 = acc[2][j] + bd;
        float v3 = acc[3][j] + bd;
        hv.x = 0.5f * v0 * (1.0f + erff(v0 * 0.7071067811865476f)) * wk;
        hv.y = 0.5f * v1 * (1.0f + erff(v1 * 0.7071067811865476f)) * wk;
        hv.z = 0.5f * v2 * (1.0f + erff(v2 * 0.7071067811865476f)) * wk;
        hv.w = 0.5f * v3 * (1.0f + erff(v3 * 0.7071067811865476f)) * wk;
        *(float4*)(hs + c * HS_STRIDE + (tr << 2)) = hv;
    }
    __syncthreads();

    // ---------------- Phase B: out = h @ Wu_cat^T (M=64, N=1024, K=128) ------
    for (int dc = 0; dc < kD; dc += 128) {
#pragma unroll
        for (int i = 0; i < 4; i++)
#pragma unroll
            for (int j = 0; j < 8; j++) acc[i][j] = 0.f;

        for (int cc = 0; cc < 128; cc += KC) {
            int cp = cc + lk;
            int e  = (cp < 64) ? e0 : e1;
            int cl = cp & 63;
            const float* wu = up_w + (size_t)e * kD * kBN + cl;
#pragma unroll
            for (int r = 0; r < 16; r++) {
                int dn = lrow + r * 8;            // 0..127
                ws[lk * WS_STRIDE + dn] = wu[(size_t)(dc + dn) * kBN];
            }
            __syncthreads();

#pragma unroll 8
            for (int kk = 0; kk < KC; kk++) {
                float4 a4 = *(const float4*)(hs + (cc + kk) * HS_STRIDE + (tr << 2));
                float4 bL = *(const float4*)(ws + kk * WS_STRIDE + (tc << 3));
                float4 bR = *(const float4*)(ws + kk * WS_STRIDE + (tc << 3) + 4);
                float a[4] = {a4.x, a4.y, a4.z, a4.w};
                float bb[8] = {bL.x, bL.y, bL.z, bL.w, bR.x, bR.y, bR.z, bR.w};
#pragma unroll
                for (int i = 0; i < 4; i++)
#pragma unroll
                    for (int j = 0; j < 8; j++)
                        acc[i][j] = fmaf(a[i], bb[j], acc[i][j]);
            }
            __syncthreads();
        }

        // Epilogue B: add combined up-bias, write out (float4 x2 per row)
        int dbase = dc + (tc << 3);
        float bias[8];
#pragma unroll
        for (int j = 0; j < 8; j++)
            bias[j] = w0 * up_b[e0 * kD + dbase + j] + w1 * up_b[e1 * kD + dbase + j];

#pragma unroll
        for (int i = 0; i < 4; i++) {
            int s = s0 + (tr << 2) + i;
            float* op = out + ((size_t)b * kS + s) * kD + dbase;
            float4 v0, v1;
            v0.x = acc[i][0] + bias[0];
            v0.y = acc[i][1] + bias[1];
            v0.z = acc[i][2] + bias[2];
            v0.w = acc[i][3] + bias[3];
            v1.x = acc[i][4] + bias[4];
            v1.y = acc[i][5] + bias[5];
            v1.z = acc[i][6] + bias[6];
            v1.w = acc[i][7] + bias[7];
            *(float4*)(op)     = v0;
            *(float4*)(op + 4) = v1;
        }
    }
}

// ---------------------------------------------------------------------------
extern "C" void kernel_launch(void* const* d_in, const int* in_sizes, int n_in,
                              void* d_out, int out_size) {
    (void)in_sizes; (void)n_in; (void)out_size;
    const float* x      = (const float*)d_in[0];
    const float* gate_w = (const float*)d_in[1];
    const float* down_w = (const float*)d_in[2];
    const float* down_b = (const float*)d_in[3];
    const float* up_w   = (const float*)d_in[4];
    const float* up_b   = (const float*)d_in[5];
    float* out = (float*)d_out;

    cudaFuncSetAttribute(moe_main, cudaFuncAttributeMaxDynamicSharedMemorySize,
                         SMEM_BYTES);

    pool_kernel<<<dim3(kD / 256, kB), 256>>>(x);
    route_kernel<<<1, kB * 32>>>(gate_w);
    moe_main<<<dim3(kS / TS, kB), 256, SMEM_BYTES>>>(x, down_w, down_b,
                                                     up_w, up_b, out);
}

// round 3
// speedup vs baseline: 3.1771x; 3.1771x over previous
#include <cuda_runtime.h>
#include <math.h>

namespace {
constexpr int kB  = 32;
constexpr int kS  = 2048;
constexpr int kD  = 1024;
constexpr int kBN = 64;
constexpr int kE  = 8;

constexpr int TS = 64;    // S rows per block
constexpr int TN = 128;   // concat expert cols (2*BN)
constexpr int KC = 32;    // k-chunk

// smem strides chosen so (stride mod 32) == 8 -> conflict-free 64-bit frag loads
constexpr int AS_STRIDE = 40;    // x tile     [64][40]
constexpr int BS_STRIDE = 40;    // weight tile[128][40]
constexpr int HS_STRIDE = 136;   // h tile     [64][136]
constexpr int AS_FLOATS = TS * AS_STRIDE;
constexpr int BS_FLOATS = TN * BS_STRIDE;
constexpr int HS_FLOATS = TS * HS_STRIDE;
constexpr int SMEM_FLOATS = AS_FLOATS + BS_FLOATS + HS_FLOATS;  // 16384
constexpr int SMEM_BYTES  = SMEM_FLOATS * 4;                     // 65536
}

// Scratch (allocation forbidden -> device globals)
__device__ float g_part[kB * 8 * kD];
__device__ float g_pooled[kB * kD];
__device__ int   g_top_i[kB * 2];
__device__ float g_top_w[kB * 2];

// ---------------------------------------------------------------------------
// TF32 helpers
// ---------------------------------------------------------------------------
__device__ __forceinline__ float f2tf(float f) {
    unsigned r;
    asm("cvt.rna.tf32.f32 %0, %1;" : "=r"(r) : "f"(f));
    return __uint_as_float(r);
}

__device__ __forceinline__ void mma_tf32(float* d,
                                         unsigned a0, unsigned a1,
                                         unsigned a2, unsigned a3,
                                         unsigned b0, unsigned b1) {
    asm volatile(
        "mma.sync.aligned.m16n8k8.row.col.f32.tf32.tf32.f32 "
        "{%0,%1,%2,%3}, {%4,%5,%6,%7}, {%8,%9}, {%0,%1,%2,%3};"
        : "+f"(d[0]), "+f"(d[1]), "+f"(d[2]), "+f"(d[3])
        : "r"(a0), "r"(a1), "r"(a2), "r"(a3), "r"(b0), "r"(b1));
}

__device__ __forceinline__ float gelu_exact(float v) {
    return 0.5f * v * (1.0f + erff(v * 0.7071067811865476f));
}

// ---------------------------------------------------------------------------
// Kernel 1a: partial pool.  grid = (D/256, B, 8), 256 threads.
// ---------------------------------------------------------------------------
__global__ void pool1_kernel(const float* __restrict__ x) {
    int d = blockIdx.x * 256 + threadIdx.x;
    int b = blockIdx.y;
    int z = blockIdx.z;
    const float* xp = x + ((size_t)b * kS + (size_t)z * 256) * kD + d;
    float acc[8] = {0.f,0.f,0.f,0.f,0.f,0.f,0.f,0.f};
#pragma unroll 1
    for (int s = 0; s < 256; s += 8) {
#pragma unroll
        for (int u = 0; u < 8; u++)
            acc[u] += xp[(size_t)(s + u) * kD];
    }
    float t = 0.f;
#pragma unroll
    for (int u = 0; u < 8; u++) t += acc[u];
    g_part[(b * 8 + z) * kD + d] = t;
}

// Kernel 1b: reduce partials. grid = (D/256, B).
__global__ void pool2_kernel() {
    int d = blockIdx.x * 256 + threadIdx.x;
    int b = blockIdx.y;
    float t = 0.f;
#pragma unroll
    for (int z = 0; z < 8; z++) t += g_part[(b * 8 + z) * kD + d];
    g_pooled[b * kD + d] = t * (1.0f / kS);
}

// ---------------------------------------------------------------------------
// Kernel 2: routing. 1 block, 32 warps; warp w handles batch b = w.
// ---------------------------------------------------------------------------
__global__ void route_kernel(const float* __restrict__ gate_w) {
    int b    = threadIdx.x >> 5;
    int lane = threadIdx.x & 31;

    float logits[kE];
#pragma unroll
    for (int e = 0; e < kE; e++) {
        float acc = 0.f;
        for (int d = lane; d < kD; d += 32)
            acc += g_pooled[b * kD + d] * gate_w[e * kD + d];
#pragma unroll
        for (int off = 16; off; off >>= 1)
            acc += __shfl_xor_sync(0xFFFFFFFFu, acc, off);
        logits[e] = acc;
    }

    if (lane == 0) {
        float mx = logits[0];
#pragma unroll
        for (int e = 1; e < kE; e++) mx = fmaxf(mx, logits[e]);
        float p[kE], sum = 0.f;
#pragma unroll
        for (int e = 0; e < kE; e++) { p[e] = expf(logits[e] - mx); sum += p[e]; }
        float inv_sum = 1.f / sum;
#pragma unroll
        for (int e = 0; e < kE; e++) p[e] *= inv_sum;

        int i0 = 0;
#pragma unroll
        for (int e = 1; e < kE; e++) if (p[e] > p[i0]) i0 = e;
        int i1 = (i0 == 0) ? 1 : 0;
#pragma unroll
        for (int e = 0; e < kE; e++) if (e != i0 && p[e] > p[i1]) i1 = e;

        float w0 = p[i0], w1 = p[i1];
        float inv = 1.f / (w0 + w1 + 1e-8f);
        g_top_i[b * 2 + 0] = i0;
        g_top_i[b * 2 + 1] = i1;
        g_top_w[b * 2 + 0] = w0 * inv;
        g_top_w[b * 2 + 1] = w1 * inv;
    }
}

// ---------------------------------------------------------------------------
// Kernel 3: fused expert MLP on TF32 tensor cores.
// grid = (S/64, B), 256 threads = 8 warps in a 2x4 grid, 32x32 warp tiles.
// k-permutation: mma slot col c holds physical k=2c, slot c+4 holds k=2c+1,
// applied identically to A cols and B rows -> 64-bit fragment loads.
// ---------------------------------------------------------------------------
__global__ __launch_bounds__(256, 2)
void moe_main(const float* __restrict__ x,
              const float* __restrict__ down_w,
              const float* __restrict__ down_b,
              const float* __restrict__ up_w,
              const float* __restrict__ up_b,
              float* __restrict__ out)
{
    extern __shared__ float smem[];
    float* As = smem;                             // [64][40]   x tile (k-chunk)
    float* Bs = smem + AS_FLOATS;                 // [128][40]  weight tile
    float* Hs = smem + AS_FLOATS + BS_FLOATS;     // [64][136]  h (s-major)

    const int b   = blockIdx.y;
    const int s0  = blockIdx.x * TS;
    const int tid = threadIdx.x;
    const int warp = tid >> 5, lane = tid & 31;
    const int wm = warp >> 2, wn = warp & 3;      // 2 x 4 warp grid
    const int q  = lane >> 2, lc = lane & 3;      // quad row / k-slot
    const int mb = wm * 32,  nb = wn * 32;

    const int ldr  = tid >> 3;                    // staging row (0..31)
    const int ldc4 = (tid & 7) * 4;               // staging col (float4)

    const int   e0 = g_top_i[2 * b + 0];
    const int   e1 = g_top_i[2 * b + 1];
    const float w0 = g_top_w[2 * b + 0];
    const float w1 = g_top_w[2 * b + 1];

    const float* xb = x + ((size_t)b * kS + s0) * kD;

    float acc[2][4][4];
#pragma unroll
    for (int i = 0; i < 2; i++)
#pragma unroll
        for (int j = 0; j < 4; j++)
#pragma unroll
            for (int r = 0; r < 4; r++) acc[i][j][r] = 0.f;

    // ================= Phase A: h = gelu(x @ Wd^T + bd) * wk =================
    for (int kc = 0; kc < kD; kc += KC) {
        // stage x tile [m][k]
#pragma unroll
        for (int p = 0; p < 2; p++) {
            int m = p * 32 + ldr;
            float4 v = *(const float4*)(xb + (size_t)m * kD + kc + ldc4);
            float* dst = As + m * AS_STRIDE + ldc4;
            dst[0] = f2tf(v.x); dst[1] = f2tf(v.y);
            dst[2] = f2tf(v.z); dst[3] = f2tf(v.w);
        }
        // stage Wd tile [n][k] (n = concat expert col)
#pragma unroll
        for (int p = 0; p < 4; p++) {
            int n = p * 32 + ldr;
            const float* wsrc = (n < 64)
                ? down_w + ((size_t)e0 * kBN + n) * kD
                : down_w + ((size_t)e1 * kBN + (n - 64)) * kD;
            float4 v = *(const float4*)(wsrc + kc + ldc4);
            float* dst = Bs + n * BS_STRIDE + ldc4;
            dst[0] = f2tf(v.x); dst[1] = f2tf(v.y);
            dst[2] = f2tf(v.z); dst[3] = f2tf(v.w);
        }
        __syncthreads();

#pragma unroll
        for (int ks = 0; ks < 4; ks++) {
            int kk = ks * 8 + 2 * lc;
            unsigned a[2][4];
#pragma unroll
            for (int i = 0; i < 2; i++) {
                float2 t0 = *(const float2*)(As + (mb + i*16 + q)     * AS_STRIDE + kk);
                float2 t1 = *(const float2*)(As + (mb + i*16 + q + 8) * AS_STRIDE + kk);
                a[i][0] = __float_as_uint(t0.x); a[i][2] = __float_as_uint(t0.y);
                a[i][1] = __float_as_uint(t1.x); a[i][3] = __float_as_uint(t1.y);
            }
#pragma unroll
            for (int j = 0; j < 4; j++) {
                float2 tb = *(const float2*)(Bs + (nb + j*8 + q) * BS_STRIDE + kk);
                unsigned b0 = __float_as_uint(tb.x), b1 = __float_as_uint(tb.y);
                mma_tf32(acc[0][j], a[0][0], a[0][1], a[0][2], a[0][3], b0, b1);
                mma_tf32(acc[1][j], a[1][0], a[1][1], a[1][2], a[1][3], b0, b1);
            }
        }
        __syncthreads();
    }

    // Epilogue A: bias + exact GELU + routing weight -> Hs[s][c'] (tf32 bits)
    {
        const float wk = (nb < 64) ? w0 : w1;     // warp tile never crosses 64
#pragma unroll
        for (int j = 0; j < 4; j++) {
            int n0 = nb + j * 8 + 2 * lc;
            float bd0 = (n0 < 64) ? down_b[e0 * kBN + n0]
                                  : down_b[e1 * kBN + n0 - 64];
            float bd1 = (n0 < 64) ? down_b[e0 * kBN + n0 + 1]
                                  : down_b[e1 * kBN + n0 - 63];
#pragma unroll
            for (int i = 0; i < 2; i++) {
                int r = mb + i * 16 + q;
                float2 h0, h1;
                h0.x = f2tf(gelu_exact(acc[i][j][0] + bd0) * wk);
                h0.y = f2tf(gelu_exact(acc[i][j][1] + bd1) * wk);
                h1.x = f2tf(gelu_exact(acc[i][j][2] + bd0) * wk);
                h1.y = f2tf(gelu_exact(acc[i][j][3] + bd1) * wk);
                *(float2*)(Hs + r       * HS_STRIDE + n0) = h0;
                *(float2*)(Hs + (r + 8) * HS_STRIDE + n0) = h1;
            }
        }
    }
    __syncthreads();

    // ================= Phase B: out = h @ Wu_cat^T + bias ====================
    for (int dc = 0; dc < kD; dc += 128) {
#pragma unroll
        for (int i = 0; i < 2; i++)
#pragma unroll
            for (int j = 0; j < 4; j++)
#pragma unroll
                for (int r = 0; r < 4; r++) acc[i][j][r] = 0.f;

        for (int cc = 0; cc < 128; cc += KC) {
            const int   e  = (cc < 64) ? e0 : e1;
            const int   cl = cc & 63;
            const float* wu = up_w + (size_t)e * kD * kBN + cl;  // [d][c]
#pragma unroll
            for (int p = 0; p < 4; p++) {
                int n = p * 32 + ldr;                            // d within chunk
                float4 v = *(const float4*)(wu + (size_t)(dc + n) * kBN + ldc4);
                float* dst = Bs + n * BS_STRIDE + ldc4;
                dst[0] = f2tf(v.x); dst[1] = f2tf(v.y);
                dst[2] = f2tf(v.z); dst[3] = f2tf(v.w);
            }
            __syncthreads();

#pragma unroll
            for (int ks = 0; ks < 4; ks++) {
                int kk  = ks * 8 + 2 * lc;
                int kkh = cc + kk;
                unsigned a[2][4];
#pragma unroll
                for (int i = 0; i < 2; i++) {
                    float2 t0 = *(const float2*)(Hs + (mb + i*16 + q)     * HS_STRIDE + kkh);
                    float2 t1 = *(const float2*)(Hs + (mb + i*16 + q + 8) * HS_STRIDE + kkh);
                    a[i][0] = __float_as_uint(t0.x); a[i][2] = __float_as_uint(t0.y);
                    a[i][1] = __float_as_uint(t1.x); a[i][3] = __float_as_uint(t1.y);
                }
#pragma unroll
                for (int j = 0; j < 4; j++) {
                    float2 tb = *(const float2*)(Bs + (nb + j*8 + q) * BS_STRIDE + kk);
                    unsigned b0 = __float_as_uint(tb.x), b1 = __float_as_uint(tb.y);
                    mma_tf32(acc[0][j], a[0][0], a[0][1], a[0][2], a[0][3], b0, b1);
                    mma_tf32(acc[1][j], a[1][0], a[1][1], a[1][2], a[1][3], b0, b1);
                }
            }
            __syncthreads();
        }

        // Epilogue B: combined up-bias, write out
#pragma unroll
        for (int j = 0; j < 4; j++) {
            int n0 = dc + nb + j * 8 + 2 * lc;
            float bias0 = w0 * up_b[e0 * kD + n0]     + w1 * up_b[e1 * kD + n0];
            float bias1 = w0 * up_b[e0 * kD + n0 + 1] + w1 * up_b[e1 * kD + n0 + 1];
#pragma unroll
            for (int i = 0; i < 2; i++) {
                int r = s0 + mb + i * 16 + q;
                float* op0 = out + ((size_t)b * kS + r)     * kD + n0;
                float* op1 = out + ((size_t)b * kS + r + 8) * kD + n0;
                float2 v0, v1;
                v0.x = acc[i][j][0] + bias0; v0.y = acc[i][j][1] + bias1;
                v1.x = acc[i][j][2] + bias0; v1.y = acc[i][j][3] + bias1;
                *(float2*)op0 = v0;
                *(float2*)op1 = v1;
            }
        }
    }
}

// ---------------------------------------------------------------------------
extern "C" void kernel_launch(void* const* d_in, const int* in_sizes, int n_in,
                              void* d_out, int out_size) {
    (void)in_sizes; (void)n_in; (void)out_size;
    const float* x      = (const float*)d_in[0];
    const float* gate_w = (const float*)d_in[1];
    const float* down_w = (const float*)d_in[2];
    const float* down_b = (const float*)d_in[3];
    const float* up_w   = (const float*)d_in[4];
    const float* up_b   = (const float*)d_in[5];
    float* out = (float*)d_out;

    cudaFuncSetAttribute(moe_main, cudaFuncAttributeMaxDynamicSharedMemorySize,
                         SMEM_BYTES);

    pool1_kernel<<<dim3(kD / 256, kB, 8), 256>>>(x);
    pool2_kernel<<<dim3(kD / 256, kB), 256>>>();
    route_kernel<<<1, kB * 32>>>(gate_w);
    moe_main<<<dim3(kS / TS, kB), 256, SMEM_BYTES>>>(x, down_w, down_b,
                                                     up_w, up_b, out);
}